// round 17
// baseline (speedup 1.0000x reference)
#include <cuda_runtime.h>
#include <cstdint>

constexpr int B = 8192;    // batch
constexpr int D = 4096;    // features
constexpr int H = 2048;    // hidden
constexpr int HW = H / 32; // 64 packed words

// Device-global scratch (no runtime allocation allowed)
__device__ uint32_t g_Wcols[D * HW];     // Wb column d packed along h (1 MB)
__device__ float    g_template[D];       // layer-2 output row for all-ones h
__device__ uint32_t g_m1[HW], g_m2[HW], g_m3[HW], g_m4[HW], g_mall[HW];
__device__ int      g_t2[D];
__device__ int      g_t1u;               // uniform layer-1 threshold in {1,2}, else -1

// ---------------------------------------------------------------------------
// Kernel 1: pack W + template + t2 (blocks 0..127) and masks/t1u (block 128).
// (Round-14 proven version, unchanged.)
// ---------------------------------------------------------------------------
__global__ void __launch_bounds__(512) pack_kernel(const float* __restrict__ W,
                                                   const float* __restrict__ be,
                                                   const float* __restrict__ b0,
                                                   const float* __restrict__ b3) {
    if (blockIdx.x < 128) {
        __shared__ uint32_t s[32][65];    // [col][word], stride 65: conflict-free
        __shared__ int scnt[32][16];      // per-col popc partials per warp
        int t    = threadIdx.x;
        int lane = t & 31;                // column
        int wg   = t >> 5;                // warp 0..15, owns words wg*4..wg*4+3
        int d0   = blockIdx.x * 32;

        int pcnt = 0;
#pragma unroll
        for (int k = 0; k < 4; k++) {
            int w = wg * 4 + k;           // word index, rows w*32..w*32+31
            const float* Wp = W + (size_t)(w * 32) * D + d0 + lane;
            float fv[32];
#pragma unroll
            for (int r = 0; r < 32; r++)  // 32 independent coalesced loads
                fv[r] = __ldcs(Wp + (size_t)r * D);
            uint32_t u = 0;
#pragma unroll
            for (int r = 0; r < 32; r++)
                if (fv[r] >= 0.5f) u |= (1u << r);
            s[lane][w] = u;
            pcnt += __popc(u);
        }
        scnt[lane][wg] = pcnt;
        __syncthreads();

        // Store Wcols: 512 threads write 512 uint4 (full-sector writes, 1 MB).
        {
            int col = t >> 4, j = t & 15;
            uint4 v = make_uint4(s[col][j * 4 + 0], s[col][j * 4 + 1],
                                 s[col][j * 4 + 2], s[col][j * 4 + 3]);
            reinterpret_cast<uint4*>(g_Wcols)[(size_t)(d0 + col) * 16 + j] = v;
        }

        // Template + t2 for this block's 32 columns.
        if (t < 32) {
            int c = 0;
#pragma unroll
            for (int wgi = 0; wgi < 16; wgi++) c += scnt[t][wgi];
            int d = d0 + t;
            int t2 = (int)ceilf(1.0f - b3[d]);
            g_t2[d] = t2;
            g_template[d] = (c >= t2) ? 1.0f : 0.0f;
        }
    } else {
        // Block 128: layer-1 threshold masks + uniformity flag.
        __shared__ int s_ok;
        int t = threadIdx.x;
        if (t == 0) s_ok = 1;
        __syncthreads();

        int t0 = (int)ceilf(1.0f - be[0] - b0[0]);

        if (t < HW) {
            uint32_t m1 = 0, m2 = 0, m3 = 0, m4 = 0, mall = 0;
#pragma unroll
            for (int bit = 0; bit < 32; bit++) {
                int h = t * 32 + bit;
                int ti = (int)ceilf(1.0f - be[h] - b0[h]);
                uint32_t m = 1u << bit;
                if (ti <= 0)      mall |= m;
                else if (ti == 1) m1 |= m;
                else if (ti == 2) m2 |= m;
                else if (ti == 3) m3 |= m;
                else if (ti == 4) m4 |= m;
            }
            g_m1[t] = m1; g_m2[t] = m2; g_m3[t] = m3; g_m4[t] = m4; g_mall[t] = mall;
        }

        int ok = 1;
        for (int h = t; h < H; h += 512) {
            int ti = (int)ceilf(1.0f - be[h] - b0[h]);
            if (ti != t0) ok = 0;
        }
        if (!ok) s_ok = 0;   // benign race, all writers store 0
        __syncthreads();
        if (t == 0) g_t1u = (s_ok && t0 >= 1 && t0 <= 2) ? t0 : -1;
    }
}

// ---------------------------------------------------------------------------
// Kernel 2 (fused layer1+layer2): one warp per batch row, 8 rows per block.
// Round-15 proven body (MLP-4 batched CSA loads).  Deltas this round:
//  (a) plain stores (evict-normal) instead of __stcs — let the 126MB L2
//      buffer the 128MB output as dirty lines instead of pushing to DRAM;
//  (b) template preload sunk to the store phase (shorter live range).
// ---------------------------------------------------------------------------
__global__ void __launch_bounds__(256) fused_kernel(const float* __restrict__ x,
                                                    float* __restrict__ out) {
    __shared__ uint32_t sh_h[8][HW];   // slow-path h bits (rarely used)
    __shared__ int sflag[8];           // per-row "broadcast template" flag
    int tid  = threadIdx.x;
    int warp = tid >> 5;
    int lane = tid & 31;
    int b = blockIdx.x * 8 + warp;

    const float4* xr = reinterpret_cast<const float4*>(x + (size_t)b * D);
    const uint2*  Wc = reinterpret_cast<const uint2*>(g_Wcols);
    int uni = g_t1u;

    uint2 c1 = make_uint2(0u, 0u), c2 = make_uint2(0u, 0u);
    uint2 c3 = make_uint2(0u, 0u), c4 = make_uint2(0u, 0u);
    bool sat = false;

    float4 f = xr[lane];                       // prefetch chunk 0
    for (int i = 0; i < 32; i++) {
        float4 cur = f;
        if (i + 1 < 32) f = xr[(i + 1) * 32 + lane];   // prefetch next chunk

        uint32_t mw0 = __ballot_sync(0xffffffffu, cur.x != 0.0f);
        uint32_t mw1 = __ballot_sync(0xffffffffu, cur.y != 0.0f);
        uint32_t mw2 = __ballot_sync(0xffffffffu, cur.z != 0.0f);
        uint32_t mw3 = __ballot_sync(0xffffffffu, cur.w != 0.0f);
        int base = i * 128;

        if (uni >= 1) {
            // 2-plane CSA; 4 predicated independent loads per iteration.
            while (mw0 | mw1 | mw2 | mw3) {
                bool p0 = mw0 != 0, p1 = mw1 != 0, p2 = mw2 != 0, p3 = mw3 != 0;
                uint2 v0, v1, v2, v3;
                if (p0) { int l = __ffs(mw0) - 1; mw0 &= mw0 - 1;
                          v0 = Wc[(base + l * 4 + 0) * 32 + lane]; }
                if (p1) { int l = __ffs(mw1) - 1; mw1 &= mw1 - 1;
                          v1 = Wc[(base + l * 4 + 1) * 32 + lane]; }
                if (p2) { int l = __ffs(mw2) - 1; mw2 &= mw2 - 1;
                          v2 = Wc[(base + l * 4 + 2) * 32 + lane]; }
                if (p3) { int l = __ffs(mw3) - 1; mw3 &= mw3 - 1;
                          v3 = Wc[(base + l * 4 + 3) * 32 + lane]; }
                if (p0) { c2.x |= c1.x & v0.x; c1.x |= v0.x;
                          c2.y |= c1.y & v0.y; c1.y |= v0.y; }
                if (p1) { c2.x |= c1.x & v1.x; c1.x |= v1.x;
                          c2.y |= c1.y & v1.y; c1.y |= v1.y; }
                if (p2) { c2.x |= c1.x & v2.x; c1.x |= v2.x;
                          c2.y |= c1.y & v2.y; c1.y |= v2.y; }
                if (p3) { c2.x |= c1.x & v3.x; c1.x |= v3.x;
                          c2.y |= c1.y & v3.y; c1.y |= v3.y; }
            }
            uint32_t sw = (uni == 1) ? (c1.x & c1.y) : (c2.x & c2.y);
            if (__all_sync(0xffffffffu, sw == 0xffffffffu)) { sat = true; break; }
        } else {
            // general 4-plane saturating CSA, same batched-load structure
            while (mw0 | mw1 | mw2 | mw3) {
                bool p0 = mw0 != 0, p1 = mw1 != 0, p2 = mw2 != 0, p3 = mw3 != 0;
                uint2 v0, v1, v2, v3;
                if (p0) { int l = __ffs(mw0) - 1; mw0 &= mw0 - 1;
                          v0 = Wc[(base + l * 4 + 0) * 32 + lane]; }
                if (p1) { int l = __ffs(mw1) - 1; mw1 &= mw1 - 1;
                          v1 = Wc[(base + l * 4 + 1) * 32 + lane]; }
                if (p2) { int l = __ffs(mw2) - 1; mw2 &= mw2 - 1;
                          v2 = Wc[(base + l * 4 + 2) * 32 + lane]; }
                if (p3) { int l = __ffs(mw3) - 1; mw3 &= mw3 - 1;
                          v3 = Wc[(base + l * 4 + 3) * 32 + lane]; }
                if (p0) { c4.x |= c3.x & v0.x; c3.x |= c2.x & v0.x; c2.x |= c1.x & v0.x; c1.x |= v0.x;
                          c4.y |= c3.y & v0.y; c3.y |= c2.y & v0.y; c2.y |= c1.y & v0.y; c1.y |= v0.y; }
                if (p1) { c4.x |= c3.x & v1.x; c3.x |= c2.x & v1.x; c2.x |= c1.x & v1.x; c1.x |= v1.x;
                          c4.y |= c3.y & v1.y; c3.y |= c2.y & v1.y; c2.y |= c1.y & v1.y; c1.y |= v1.y; }
                if (p2) { c4.x |= c3.x & v2.x; c3.x |= c2.x & v2.x; c2.x |= c1.x & v2.x; c1.x |= v2.x;
                          c4.y |= c3.y & v2.y; c3.y |= c2.y & v2.y; c2.y |= c1.y & v2.y; c1.y |= v2.y; }
                if (p3) { c4.x |= c3.x & v3.x; c3.x |= c2.x & v3.x; c2.x |= c1.x & v3.x; c1.x |= v3.x;
                          c4.y |= c3.y & v3.y; c3.y |= c2.y & v3.y; c2.y |= c1.y & v3.y; c1.y |= v3.y; }
            }
            if (__all_sync(0xffffffffu, (c4.x & c4.y) == 0xffffffffu)) break;
        }
    }

    // Resolve hidden bits for this row
    uint2 hw;
    if (uni >= 1) {
        hw = sat ? make_uint2(0xffffffffu, 0xffffffffu) : ((uni == 1) ? c1 : c2);
    } else {
        int w0 = 2 * lane, w1 = 2 * lane + 1;
        hw.x = g_mall[w0] | (c1.x & g_m1[w0]) | (c2.x & g_m2[w0]) |
               (c3.x & g_m3[w0]) | (c4.x & g_m4[w0]);
        hw.y = g_mall[w1] | (c1.y & g_m1[w1]) | (c2.y & g_m2[w1]) |
               (c3.y & g_m3[w1]) | (c4.y & g_m4[w1]);
    }
    bool allones = __all_sync(0xffffffffu, (hw.x & hw.y) == 0xffffffffu);
    if (lane == 0) sflag[warp] = allones ? 1 : 0;

    if (!allones) {
        // exact path (rare): popcount h against every Wb column
        sh_h[warp][2 * lane]     = hw.x;
        sh_h[warp][2 * lane + 1] = hw.y;
        __syncwarp();
        const uint32_t* hv = sh_h[warp];
        for (int k = 0; k < D / 32; k++) {
            int d = k * 32 + lane;
            int t2 = g_t2[d];
            float val;
            if (t2 <= 0) {
                val = 1.0f;
            } else {
                const uint32_t* wv = g_Wcols + (size_t)d * HW;
                int c = 0;
                for (int w = 0; w < HW; w++) {
                    c += __popc(hv[w] & wv[w]);
                    if (c >= t2) break;
                }
                val = (c >= t2) ? 1.0f : 0.0f;
            }
            out[(size_t)b * D + d] = val;
        }
    }
    __syncthreads();

    // Template load sunk here (short live range), then block-cooperative
    // broadcast with DEFAULT stores — dirty lines may stay in L2.
    const float4* tp = reinterpret_cast<const float4*>(g_template);
    float4 tpl0 = __ldg(&tp[tid]);
    float4 tpl1 = __ldg(&tp[tid + 256]);
    float4 tpl2 = __ldg(&tp[tid + 512]);
    float4 tpl3 = __ldg(&tp[tid + 768]);

#pragma unroll
    for (int r = 0; r < 8; r++) {
        if (sflag[r]) {
            float4* orow = reinterpret_cast<float4*>(out + (size_t)(blockIdx.x * 8 + r) * D);
            orow[tid]       = tpl0;
            orow[tid + 256] = tpl1;
            orow[tid + 512] = tpl2;
            orow[tid + 768] = tpl3;
        }
    }
}

// ---------------------------------------------------------------------------
extern "C" void kernel_launch(void* const* d_in, const int* in_sizes, int n_in,
                              void* d_out, int out_size) {
    const float* x     = (const float*)d_in[0];  // [B, D]
    const float* W     = (const float*)d_in[1];  // [H, D]
    const float* b_enc = (const float*)d_in[2];  // [H]
    const float* b0    = (const float*)d_in[3];  // [H]
    const float* b3    = (const float*)d_in[4];  // [D]
    float* out = (float*)d_out;                  // [B, D]

    pack_kernel<<<129, 512>>>(W, b_enc, b0, b3);
    fused_kernel<<<B / 8, 256>>>(x, out);
}